// round 11
// baseline (speedup 1.0000x reference)
#include <cuda_runtime.h>

#define EPS 0.1f
#define BB 64
#define II 1024
#define HH 4096
#define OO 256

__device__ float        g_w1norm[HH];
__device__ unsigned int g_done[4];   // zero-init; per replay: 0 -> 128 -> reset 0
__device__ unsigned int g_acks[4];   // zero-init; per replay: 0 -> 256 -> reset 0

// ---------------------------------------------------------------------------
// One fused kernel, grid = 512 + 256 + 1024 = 1792 blocks x 256 threads.
//   bid <  512        : w1norm rows [8b, 8b+8) (warp-per-row, 8 LDG.128 in
//                       flight). chunk = b>>7. fence + done[chunk]++.
//                       First in bid order -> all wave-1 resident -> never
//                       blocked by spinners -> no deadlock.
//   512 <= bid < 768  : nn_output row i = bid-512 (independent, no wait).
//   bid >= 768        : pert unit p = bid-768 (i=p>>2, c=p&3). Loads W2/y
//                       first, spins on done[c]==128, then the exact R2/R3
//                       store stream. 256th acker per chunk resets the flags
//                       for the next graph replay (all waiters have passed).
// ---------------------------------------------------------------------------
__global__ void __launch_bounds__(256)
k_fused(const int*   __restrict__ y,
        const float* __restrict__ W1,
        const float* __restrict__ W2,
        const float* __restrict__ bias2,
        float* __restrict__ out_nn,
        float* __restrict__ pert)
{
    const int bid = blockIdx.x;
    const int tid = threadIdx.x;
    const int lid = tid & 31;
    const int wid = tid >> 5;

    if (bid < 512) {
        // ---------------- w1norm ----------------
        const int row = bid * 8 + wid;
        const float4* r = reinterpret_cast<const float4*>(W1 + (size_t)row * II);
        float4 v[8];
        #pragma unroll
        for (int k = 0; k < 8; k++) v[k] = r[lid + k * 32];
        float s = 0.f;
        #pragma unroll
        for (int k = 0; k < 8; k++)
            s += fabsf(v[k].x) + fabsf(v[k].y) + fabsf(v[k].z) + fabsf(v[k].w);
        #pragma unroll
        for (int o = 16; o; o >>= 1) s += __shfl_down_sync(0xffffffffu, s, o);
        if (lid == 0) g_w1norm[row] = s;
        __syncthreads();
        __threadfence();                       // publish norms before flag
        if (tid == 0) atomicAdd(&g_done[bid >> 7], 1u);
        return;
    }

    if (bid < 768) {
        // ---------------- nn_output row i (no dependency) ----------------
        const int i = bid - 512;
        const float4* r = reinterpret_cast<const float4*>(W2 + (size_t)i * HH);
        float4 v[4];
        #pragma unroll
        for (int k = 0; k < 4; k++) v[k] = r[tid + k * 256];
        float s = 0.f;
        #pragma unroll
        for (int k = 0; k < 4; k++) s += v[k].x + v[k].y + v[k].z + v[k].w;

        __shared__ float sm[8];
        #pragma unroll
        for (int o = 16; o; o >>= 1) s += __shfl_down_sync(0xffffffffu, s, o);
        if (lid == 0) sm[wid] = s;
        __syncthreads();
        __shared__ float total;
        if (tid < 8) {
            float t = sm[tid];
            #pragma unroll
            for (int o = 4; o; o >>= 1) t += __shfl_down_sync(0xffu, t, o);
            if (tid == 0) total = t * (float)HH + bias2[i];
        }
        __syncthreads();
        if (tid < BB)
            out_nn[(size_t)tid * OO + i] = total;
        return;
    }

    // ---------------- pert ----------------
    const int p  = bid - 768;
    const int i  = p >> 2;
    const int c  = p & 3;
    const int j4 = c * 256 + tid;

    __shared__ float yf[BB];
    if (tid < BB) yf[tid] = (float)y[(size_t)tid * OO + i];

    // independent load first (overlaps the wait)
    float4 w = reinterpret_cast<const float4*>(W2 + (size_t)i * HH)[j4];

    // wait for this chunk's norms
    if (tid == 0) {
        while (*(volatile unsigned int*)&g_done[c] < 128u)
            __nanosleep(128);
        __threadfence();                       // acquire norms
        // ack; 256th acker (unique this replay) resets flags for next replay
        if (atomicAdd(&g_acks[c], 1u) == 255u) {
            *(volatile unsigned int*)&g_done[c] = 0u;
            *(volatile unsigned int*)&g_acks[c] = 0u;
        }
    }
    __syncthreads();                           // releases wait + covers yf

    float4 n = reinterpret_cast<const float4*>(g_w1norm)[j4];
    float4 s;
    s.x = -EPS * ((w.x > 0.f) ? 1.f : (w.x < 0.f) ? -1.f : 0.f) * n.x;
    s.y = -EPS * ((w.y > 0.f) ? 1.f : (w.y < 0.f) ? -1.f : 0.f) * n.y;
    s.z = -EPS * ((w.z > 0.f) ? 1.f : (w.z < 0.f) ? -1.f : 0.f) * n.z;
    s.w = -EPS * ((w.w > 0.f) ? 1.f : (w.w < 0.f) ? -1.f : 0.f) * n.w;

    float* base = pert + (size_t)i * HH + (size_t)j4 * 4;
    #pragma unroll 8
    for (int b = 0; b < BB; b++) {
        float yb = yf[b];
        float4 o;
        o.x = yb * s.x; o.y = yb * s.y; o.z = yb * s.z; o.w = yb * s.w;
        __stcs(reinterpret_cast<float4*>(base + (size_t)b * OO * HH), o);
    }
}

// ---------------------------------------------------------------------------
// launch — single kernel
// inputs: x[0] (unused), y[1], W1[2], W2[3], bias1[4] (unused), bias2[5]
// out layout: nn_output [B*O] then pert [B*O*H]
// ---------------------------------------------------------------------------
extern "C" void kernel_launch(void* const* d_in, const int* in_sizes, int n_in,
                              void* d_out, int out_size) {
    const int*   y     = (const int*)d_in[1];
    const float* W1    = (const float*)d_in[2];
    const float* W2    = (const float*)d_in[3];
    const float* bias2 = (const float*)d_in[5];

    float* out_nn = (float*)d_out;
    float* pert   = out_nn + (size_t)BB * OO;

    k_fused<<<512 + 256 + 1024, 256>>>(y, W1, W2, bias2, out_nn, pert);
}